// round 9
// baseline (speedup 1.0000x reference)
#include <cuda_runtime.h>
#include <math.h>

// ---------------------------------------------------------------------------
// Problem constants
// ---------------------------------------------------------------------------
#define N64   64
#define G     262144      // 64^3
#define KG    6
#define AK    768         // NATOM*KG
#define NS    33          // surviving frequencies per axis: s in [-16,16]
#define NHALF 545         // Hermitian half-spectrum columns: 16*33 + 17
#define NB    137         // persistent grid size (<= 148 SMs, 1 block/SM)

// ---------------------------------------------------------------------------
// Device scratch (static globals: no allocation allowed)
// ---------------------------------------------------------------------------
__device__ float2 g_Ft [3 * N64 * AK]; // per-axis table DFTs, [axis][k][ak]
__device__ float2 g_A  [NS * 64 * 34]; // x-inverse out: [kzs][x(stride34)][kys]
__device__ double g_sum, g_sumsq;      // spectral-domain stats (Parseval)
__device__ unsigned int          g_cnt[2];  // barrier arrive counters (self-reset)
__device__ volatile unsigned int g_gen[2];  // barrier generations (monotonic)

// Shared-memory union: phases are strictly sequential (grid barriers between).
union SmemU {
    struct { float  R[8 * 64]; } a;                       // phase A: table rows
    struct { float2 Fx[NS * 129];                         // phase B
             float2 P [4 * 128];
             float2 Sp[16 * NS];
             double Sred[132]; } b;
    struct { float2 A[NS * NS];                           // phase C
             float2 C[NS * 32]; } c;
};

// Replay-safe grid barrier. All threads fence their own prior global writes
// to device scope, then tid 0 arrives; generation compare is relative to the
// pre-arrival read, so wraps/replays are safe and g_cnt self-resets.
__device__ __forceinline__ void gbar(int i)
{
    __threadfence();
    __syncthreads();
    if (threadIdx.x == 0) {
        unsigned int my = g_gen[i];
        unsigned int t = atomicInc(&g_cnt[i], NB - 1);
        if (t == NB - 1) { __threadfence(); g_gen[i] = my + 1; }
        else             { while (g_gen[i] == my) __nanosleep(64); }
        __threadfence();
    }
    __syncthreads();
}

// ---------------------------------------------------------------------------
// The whole pipeline in one persistent kernel.
//   Phase A: Gaussian table rows -> 64-pt DFT -> g_Ft   (2304 rows)
//   Phase B: half-spectrum x Hamming + Parseval stats + fused x-inverse
//   Phase C: y-inverse + z-inverse + direct normalized write to out
// ---------------------------------------------------------------------------
__global__ void __launch_bounds__(512, 1)
k_all(const float* __restrict__ X,  const float* __restrict__ aw,
      const float* __restrict__ bw, const float* __restrict__ rgf,
      const float* __restrict__ ham, float* __restrict__ out)
{
    __shared__ SmemU U;
    __shared__ float2 Wsh[64];
    __shared__ int kyi_sh[4], kzi_sh[4];

    int tid = threadIdx.x, bid = blockIdx.x;

    if (tid < 64) {
        float ang = -2.0f * 3.14159265358979323846f * (float)tid / 64.0f;
        float s, c;
        __sincosf(ang, &s, &c);
        Wsh[tid] = make_float2(c, s);
    }
    if (bid == 0 && tid == 0) g_sumsq = 0.0;
    __syncthreads();

    // ========================= Phase A: tables =============================
    {
        int r = tid >> 6, n = tid & 63;
        for (int gg = bid; gg < 288; gg += NB) {
            int row  = gg * 8 + r;
            int axis = row / 768;
            int ak   = row - axis * 768;
            int a    = ak / KG;
            int kk   = ak - a * KG;
            float b  = bw[a * KG + kk];
            float wc = aw[a * KG + kk];
            float cc = (axis == 0) ? rgf[n * 12288]
                     : (axis == 1) ? rgf[n * 192 + 1]
                                   : rgf[n * 3 + 2];
            float d  = cc - X[a * 3 + axis];
            float v  = __expf(b * d * d);
            if (axis == 0) v *= wc;
            U.a.R[r * 64 + n] = v;
            __syncthreads();
            float2 acc = make_float2(0.f, 0.f);
            for (int m = 0; m < 64; m++) {
                float  x = U.a.R[r * 64 + m];
                float2 w = Wsh[(n * m) & 63];
                acc.x = fmaf(x, w.x, acc.x);
                acc.y = fmaf(x, w.y, acc.y);
            }
            g_Ft[axis * (N64 * AK) + n * AK + ak] = acc;
            __syncthreads();
        }
    }
    gbar(0);

    // ==================== Phase B: spectrum + x-inverse ====================
    {
        int c0 = bid * 4;
        if (tid < 4) {
            int cg = c0 + tid; if (cg > NHALF - 1) cg = NHALF - 1;
            int kzs = cg / NS, kys = cg - kzs * NS;
            kyi_sh[tid] = (kys - 16) & 63;
            kzi_sh[tid] = (kzs - 16) & 63;
        }
        __syncthreads();

        int w = tid >> 5, lane = tid & 31;
        int colw = w >> 2, q = w & 3;        // column-in-block, ak quarter
        float2 S  = make_float2(0.f, 0.f);   // kx slot = lane (sxs 0..31)
        float2 S2 = make_float2(0.f, 0.f);   // sxs = 32, lane-split partial

        for (int ch = 0; ch < 6; ch++) {
            int ak0 = ch * 128;
            for (int i = tid; i < NS * 128; i += 512) {
                int sxs = i >> 7, ak = i & 127;
                int kxi = (sxs - 16) & 63;
                U.b.Fx[sxs * 129 + ak] = g_Ft[kxi * AK + ak0 + ak];
            }
            for (int i = tid; i < 4 * 128; i += 512) {
                int col = i >> 7, ak = i & 127;
                float2 a = g_Ft[N64 * AK     + kyi_sh[col] * AK + ak0 + ak];
                float2 b = g_Ft[2 * N64 * AK + kzi_sh[col] * AK + ak0 + ak];
                U.b.P[i] = make_float2(a.x * b.x - a.y * b.y,
                                       a.x * b.y + a.y * b.x);
            }
            __syncthreads();
            {
                const float2* Pr = &U.b.P[colw * 128 + q * 32];
                const float2* Fr = &U.b.Fx[lane * 129 + q * 32];
                #pragma unroll 8
                for (int a = 0; a < 32; a++) {
                    float2 p = Pr[a], f = Fr[a];
                    S.x = fmaf(p.x, f.x, S.x); S.x = fmaf(-p.y, f.y, S.x);
                    S.y = fmaf(p.x, f.y, S.y); S.y = fmaf( p.y, f.x, S.y);
                }
                float2 p = U.b.P [colw * 128 + q * 32 + lane];
                float2 f = U.b.Fx[32 * 129  + q * 32 + lane];
                S2.x = fmaf(p.x, f.x, S2.x); S2.x = fmaf(-p.y, f.y, S2.x);
                S2.y = fmaf(p.x, f.y, S2.y); S2.y = fmaf( p.y, f.x, S2.y);
            }
            __syncthreads();
        }
        #pragma unroll
        for (int o = 16; o; o >>= 1) {
            S2.x += __shfl_xor_sync(0xFFFFFFFFu, S2.x, o);
            S2.y += __shfl_xor_sync(0xFFFFFFFFu, S2.y, o);
        }
        U.b.Sp[w * NS + lane] = S;
        if (lane == 0) U.b.Sp[w * NS + 32] = S2;
        __syncthreads();

        // combine 4 warp partials per column + Hamming + Parseval stats
        float2 v = make_float2(0.f, 0.f);
        int colc = 0, sxsc = 0;
        if (tid < 4 * NS) {
            colc = tid / NS; sxsc = tid - colc * NS;
            float2 acc = make_float2(0.f, 0.f);
            #pragma unroll
            for (int i = 0; i < 4; i++) {
                float2 t = U.b.Sp[(colc * 4 + i) * NS + sxsc];
                acc.x += t.x; acc.y += t.y;
            }
            int cgu = c0 + colc;                 // unclamped: stats guard
            int cg  = cgu > NHALF - 1 ? NHALF - 1 : cgu;
            int kzs = cg / NS, kys = cg - kzs * NS;
            int hx = (sxsc + 16) & 63, hy = (kys + 16) & 63, hz = (kzs + 16) & 63;
            float h = ham[(hx << 12) | (hy << 6) | hz];
            v = make_float2(acc.x * h, acc.y * h);
            double contrib = 0.0;
            if (cgu < NHALF) {
                double m2 = (double)v.x * v.x + (double)v.y * v.y;
                contrib = (cgu == NHALF - 1) ? m2 : 2.0 * m2;
                if (cgu == NHALF - 1 && sxsc == 16) g_sum = (double)v.x;
            }
            U.b.Sred[tid] = contrib;
        }
        __syncthreads();
        if (tid < 4 * NS) U.b.Sp[colc * NS + sxsc] = v;
        if (tid == 0) {
            double t = 0.0;
            for (int i = 0; i < 4 * NS; i++) t += U.b.Sred[i];
            atomicAdd(&g_sumsq, t);
        }
        __syncthreads();

        // fused x-inverse (rotation twiddles) + Hermitian mirror write
        if (tid < 256) {
            int col = tid >> 6, x = tid & 63;
            int cg  = c0 + col; if (cg > NHALF - 1) cg = NHALF - 1;
            float2 T  = make_float2(0.f, 0.f);
            float2 wv = Wsh[(16 * x) & 63];      // s = -16 start
            float2 ws = Wsh[(-x) & 63];          // step: * e^{+2pi i x/64}
            #pragma unroll
            for (int sxs = 0; sxs < NS; sxs++) {
                float2 s = U.b.Sp[col * NS + sxs];
                T.x = fmaf(s.x, wv.x, T.x); T.x = fmaf(-s.y, wv.y, T.x);
                T.y = fmaf(s.x, wv.y, T.y); T.y = fmaf( s.y, wv.x, T.y);
                float2 nw = make_float2(wv.x * ws.x - wv.y * ws.y,
                                        wv.x * ws.y + wv.y * ws.x);
                wv = nw;
            }
            int kzs = cg / NS, kys = cg - kzs * NS;
            g_A[kzs * 2176 + x * 34 + kys] = T;
            g_A[(32 - kzs) * 2176 + x * 34 + (32 - kys)] = make_float2(T.x, -T.y);
        }
    }
    gbar(1);

    // ============ Phase C: y/z-inverse + direct normalized write ===========
    if (bid < 128) {
        int x = bid >> 1, yh = bid & 1;
        for (int i = tid; i < NS * NS; i += 512) {
            int kzs = i / NS, kys = i - kzs * NS;
            U.c.A[i] = g_A[kzs * 2176 + x * 34 + kys];
        }
        __syncthreads();

        // y-inverse: C[kzs][yl] = sum_kys A[kzs][kys] * e^{+2pi i y sy/64}
        for (int i = tid; i < NS * 32; i += 512) {
            int yl = i & 31, kzs = i >> 5;
            int y  = yh * 32 + yl;
            float2 acc = make_float2(0.f, 0.f);
            float2 wv  = Wsh[(16 * y) & 63];
            float2 ws  = Wsh[(-y) & 63];
            #pragma unroll
            for (int kys = 0; kys < NS; kys++) {
                float2 a = U.c.A[kzs * NS + kys];
                acc.x = fmaf(a.x, wv.x, acc.x); acc.x = fmaf(-a.y, wv.y, acc.x);
                acc.y = fmaf(a.x, wv.y, acc.y); acc.y = fmaf( a.y, wv.x, acc.y);
                float2 nw = make_float2(wv.x * ws.x - wv.y * ws.y,
                                        wv.x * ws.y + wv.y * ws.x);
                wv = nw;
            }
            U.c.C[kzs * 32 + yl] = acc;
        }
        __syncthreads();

        // Parseval-domain stats:
        //   mean     = S[0]/G
        //   E[out^2] = (sum_k |S_k|^2) / G^2   (Plancherel, out = IDFT/N^3)
        double mean = g_sum / (double)G;
        double var  = g_sumsq / ((double)G * (double)G) - mean * mean;
        double stdv = sqrt(var > 0.0 ? var : 0.0);
        float  inv  = (float)(1.0 / (stdv + 1e-8));
        float  m    = (float)mean;

        int z = tid & 63, yg = tid >> 6;     // 8 y-groups of 4
        float acc4[4];
        #pragma unroll
        for (int j = 0; j < 4; j++) acc4[j] = 0.f;
        float2 wv = Wsh[(16 * z) & 63];
        float2 ws = Wsh[(-z) & 63];
        for (int kzs = 0; kzs < NS; kzs++) {
            #pragma unroll
            for (int j = 0; j < 4; j++) {
                float2 c = U.c.C[kzs * 32 + yg * 4 + j];
                acc4[j] = fmaf(c.x, wv.x, acc4[j]);
                acc4[j] = fmaf(-c.y, wv.y, acc4[j]);
            }
            float2 nw = make_float2(wv.x * ws.x - wv.y * ws.y,
                                    wv.x * ws.y + wv.y * ws.x);
            wv = nw;
        }
        const float scale = 1.0f / 262144.0f;   // combined ortho norm = 1/N^3
        #pragma unroll
        for (int j = 0; j < 4; j++) {
            float vv = acc4[j] * scale;
            int y = yh * 32 + yg * 4 + j;
            out[x * 4096 + y * 64 + z] = (vv - m) * inv;
        }
    }
}

// ---------------------------------------------------------------------------
// Launch
//   inputs: 0=X(384) 1=aw(768) 2=bw(768) 3=real_grid_flat(786432) 4=hamming(262144)
// ---------------------------------------------------------------------------
extern "C" void kernel_launch(void* const* d_in, const int* in_sizes, int n_in,
                              void* d_out, int out_size)
{
    const float* X   = (const float*)d_in[0];
    const float* aw  = (const float*)d_in[1];
    const float* bw  = (const float*)d_in[2];
    const float* rgf = (const float*)d_in[3];
    const float* ham = (const float*)d_in[4];

    k_all<<<NB, 512>>>(X, aw, bw, rgf, ham, (float*)d_out);
}